// round 7
// baseline (speedup 1.0000x reference)
#include <cuda_runtime.h>

#define NROW 8
#define ROWN (1 << 20)          // elements per batch row
#define N4   (ROWN / 4)         // float4 count per row
#define NBIN 2048
#define BPR  74                 // blocks per row -> 592 blocks ~= 4/SM, 1 wave
#define TPB  256
#define K_ALL 524288.0f         // max(1, int(N * 0.5))
#define SUMSCALE 4194304.0f     // 2^22 fixed-point scale for packed sums
#define INV_SUMSCALE 2.384185791015625e-7f   // 2^-22
#define CNT_SHIFT 44
#define SUM_MASK ((1ull << CNT_SHIFT) - 1ull)

// ---- global scratch (zero-initialized at load; tail restores zeros) ----
__device__ unsigned long long g_hist[NROW][NBIN];
__device__ float    g_sum_pos[NROW];
__device__ unsigned g_n_pos[NROW];
__device__ unsigned g_row_done[NROW];
__device__ float    g_per[NROW];
__device__ unsigned g_done;

// ---------------------------------------------------------------
// Single fused kernel: BCE + hist build; per-row last block selects.
// grid = (BPR, NROW), block = TPB
// ---------------------------------------------------------------
__global__ __launch_bounds__(TPB, 4) void ohem_fused(
    const float* __restrict__ logits,
    const int*   __restrict__ targets,
    const int*   __restrict__ mask,
    float*       __restrict__ d_out)
{
    __shared__ unsigned long long s_hist[NBIN];
    __shared__ float    r_sp[TPB / 32];
    __shared__ unsigned r_np[TPB / 32];
    __shared__ unsigned s_wc[TPB / 32], s_wca[TPB / 32];
    __shared__ float    s_wf[TPB / 32], s_wfa[TPB / 32];
    __shared__ float    sh_kept;
    __shared__ unsigned sh_nneg;
    __shared__ int      sh_last;

    const int row  = blockIdx.y;
    const int tid  = threadIdx.x;
    const int lane = tid & 31;
    const int wid  = tid >> 5;

    #pragma unroll
    for (int i = tid; i < NBIN; i += TPB) s_hist[i] = 0ull;
    __syncthreads();

    const float4* xl = (const float4*)(logits  + (size_t)row * ROWN);
    const int4*   tl = (const int4*)  (targets + (size_t)row * ROWN);
    const int4*   ml = (const int4*)  (mask    + (size_t)row * ROWN);

    float    sp = 0.f;
    unsigned np = 0u;

    const int stride = BPR * TPB;

    #pragma unroll 4
    for (int i = blockIdx.x * TPB + tid; i < N4; i += stride) {
        float4 x4 = xl[i];
        int4   t4 = tl[i];
        int4   m4 = ml[i];

        float xs[4] = {x4.x, x4.y, x4.z, x4.w};
        int   ts[4] = {t4.x, t4.y, t4.z, t4.w};
        int   ms[4] = {m4.x, m4.y, m4.z, m4.w};

        #pragma unroll
        for (int k = 0; k < 4; k++) {
            float x = xs[k];
            // stable BCE-with-logits: max(x,0) - x*t + log1p(exp(-|x|))
            float bce = fmaxf(x, 0.f) - x * (float)ts[k]
                      + __logf(1.f + __expf(-fabsf(x)));
            bce = fmaxf(bce, 0.f);

            const bool in_pos = ms[k] && ts[k];
            const bool in_neg = ms[k] && !ts[k];
            if (in_pos) { sp += bce; np++; }

            // warp-aggregated histogram update for negatives
            unsigned negmask = __ballot_sync(0xffffffffu, in_neg);
            if (in_neg) {
                unsigned bin = __float_as_uint(bce) >> 21;       // < 2048
                unsigned su  = (unsigned)(bce * SUMSCALE + 0.5f);
                unsigned peers = __match_any_sync(negmask, bin);
                unsigned cnt   = __popc(peers);
                unsigned agg   = __reduce_add_sync(peers, su);
                if (lane == (__ffs(peers) - 1)) {
                    unsigned long long pk =
                        ((unsigned long long)cnt << CNT_SHIFT)
                        + (unsigned long long)agg;
                    atomicAdd(&s_hist[bin], pk);
                }
            }
        }
    }

    // reduce positives
    #pragma unroll
    for (int o = 16; o > 0; o >>= 1) {
        sp += __shfl_down_sync(0xffffffffu, sp, o);
        np += __shfl_down_sync(0xffffffffu, np, o);
    }
    if (lane == 0) { r_sp[wid] = sp; r_np[wid] = np; }
    __syncthreads();

    if (tid == 0) {
        float bsp = 0.f; unsigned bnp = 0u;
        #pragma unroll
        for (int w = 0; w < TPB / 32; w++) { bsp += r_sp[w]; bnp += r_np[w]; }
        atomicAdd(&g_sum_pos[row], bsp);
        atomicAdd(&g_n_pos[row],   bnp);
    }

    // flush shared histogram (sparse: ~30-60 hot bins)
    for (int b = tid; b < NBIN; b += TPB) {
        unsigned long long v = s_hist[b];
        if (v) atomicAdd(&g_hist[row][b], v);
    }

    __threadfence();
    if (tid == 0) {
        unsigned old = atomicAdd(&g_row_done[row], 1u);
        sh_last = (old == BPR - 1) ? 1 : 0;
    }
    __syncthreads();
    if (!sh_last) return;

    // ============ per-row selection (last block of this row) ============
    __threadfence();   // acquire: see all other blocks' hist/accumulator writes

    const float fnpos  = (float)g_n_pos[row];
    const float sp_row = g_sum_pos[row];

    unsigned cnt8[8];
    float    sum8[8];
    unsigned csum = 0u;
    float    fsum = 0.f;
    #pragma unroll
    for (int k = 0; k < 8; k++) {
        unsigned long long v = g_hist[row][tid * 8 + k];
        cnt8[k] = (unsigned)(v >> CNT_SHIFT);
        sum8[k] = (float)(v & SUM_MASK) * INV_SUMSCALE;
        csum += cnt8[k];
        fsum += sum8[k];
    }

    // intra-warp inclusive suffix scan (lane i gets sum over lanes i..31)
    unsigned ci = csum; float fi = fsum;
    #pragma unroll
    for (int off = 1; off < 32; off <<= 1) {
        unsigned c2 = __shfl_down_sync(0xffffffffu, ci, off);
        float    f2 = __shfl_down_sync(0xffffffffu, fi, off);
        if (lane + off < 32) { ci += c2; fi += f2; }
    }
    if (lane == 0) { s_wc[wid] = ci; s_wf[wid] = fi; }
    if (tid == 0) sh_kept = 0.f;
    __syncthreads();

    if (tid == 0) {   // tiny 8-entry suffix-exclusive over warp totals
        unsigned ca = 0u; float sa = 0.f;
        for (int w = (TPB / 32) - 1; w >= 0; w--) {
            s_wca[w] = ca; s_wfa[w] = sa;
            ca += s_wc[w]; sa += s_wf[w];
        }
        sh_nneg = ca;
    }
    __syncthreads();

    const float fnneg = (float)sh_nneg;
    const float jf    = fminf(fmaxf(K_ALL - fnpos, 0.f), fnneg);
    const unsigned ju = (unsigned)jf;

    if (ju > 0u) {
        // exclusive "strictly above this thread's chunk"
        unsigned ca = s_wca[wid] + (ci - csum);
        float    sa = s_wfa[wid] + (fi - fsum);
        #pragma unroll
        for (int k = 7; k >= 0; k--) {   // walk bins high -> low
            unsigned c = cnt8[k];
            if (c && ca < ju && ca + c >= ju) {
                float r    = (float)(ju - ca);
                float mean = sum8[k] / (float)c;
                sh_kept = sa + r * mean;     // exactly one thread matches
            }
            ca += c;
            sa += sum8[k];
        }
    }

    // cleanup for next graph replay (all reads of this row's globals done)
    #pragma unroll
    for (int k = 0; k < 8; k++) g_hist[row][tid * 8 + k] = 0ull;
    if (tid == 0) {
        g_sum_pos[row]  = 0.f;
        g_n_pos[row]    = 0u;
        g_row_done[row] = 0u;
    }
    __syncthreads();

    if (tid == 0) {
        float kkeep = fnpos + jf;
        float ps = (kkeep > 0.f)
                 ? (sp_row + sh_kept) / fmaxf(kkeep, 1.f)
                 : 0.f;
        g_per[row] = ps;
        __threadfence();
        unsigned old = atomicAdd(&g_done, 1u);
        if (old == NROW - 1) {
            __threadfence();
            g_done = 0u;                  // reset for next replay
            volatile float* vp = g_per;
            float tot = 0.f;
            #pragma unroll
            for (int r = 0; r < NROW; r++) tot += vp[r];
            d_out[0] = tot * (1.f / (float)NROW);
        }
    }
}

// ---------------------------------------------------------------
extern "C" void kernel_launch(void* const* d_in, const int* in_sizes, int n_in,
                              void* d_out, int out_size)
{
    (void)in_sizes; (void)n_in; (void)out_size;
    const float* logits  = (const float*)d_in[0];
    const int*   targets = (const int*)d_in[1];
    const int*   mask    = (const int*)d_in[2];
    float*       out     = (float*)d_out;

    dim3 grid(BPR, NROW);
    ohem_fused<<<grid, TPB>>>(logits, targets, mask, out);
}

// round 8
// speedup vs baseline: 1.5357x; 1.5357x over previous
#include <cuda_runtime.h>

#define NROW 8
#define ROWN (1 << 20)          // elements per batch row
#define N4   (ROWN / 4)         // float4 count per row
#define NBIN 2048
#define NCOPY 2                 // shared-hist copies (warp parity)
#define BPR  64                 // stride 16384 -> exactly 16 iters (compile-time)
#define TPB  256
#define ITERS (N4 / (BPR * TPB))   // 16
#define K_ALL 524288.0f         // max(1, int(N * 0.5))
#define SUMSCALE 4194304.0f     // 2^22 fixed-point scale for packed sums
#define INV_SUMSCALE 2.384185791015625e-7f   // 2^-22
#define CNT_SHIFT 44
#define SUM_MASK ((1ull << CNT_SHIFT) - 1ull)

// ---- global scratch (zero-initialized at load; tail restores zeros) ----
__device__ unsigned long long g_hist[NROW][NBIN];
__device__ float    g_sum_pos[NROW];
__device__ unsigned g_n_pos[NROW];
__device__ unsigned g_row_done[NROW];
__device__ float    g_per[NROW];
__device__ unsigned g_done;

// ---------------------------------------------------------------
// Single fused kernel: BCE + hist build; per-row last block selects.
// grid = (BPR, NROW), block = TPB
// ---------------------------------------------------------------
__global__ __launch_bounds__(TPB, 4) void ohem_fused(
    const float* __restrict__ logits,
    const int*   __restrict__ targets,
    const int*   __restrict__ mask,
    float*       __restrict__ d_out)
{
    __shared__ unsigned long long s_hist[NCOPY][NBIN];
    __shared__ float    r_sp[TPB / 32];
    __shared__ unsigned r_np[TPB / 32];
    __shared__ unsigned s_wc[TPB / 32], s_wca[TPB / 32];
    __shared__ float    s_wf[TPB / 32], s_wfa[TPB / 32];
    __shared__ float    sh_kept;
    __shared__ unsigned sh_nneg;
    __shared__ int      sh_last;

    const int row  = blockIdx.y;
    const int tid  = threadIdx.x;
    const int lane = tid & 31;
    const int wid  = tid >> 5;

    {
        unsigned long long* p = &s_hist[0][0];
        #pragma unroll
        for (int i = tid; i < NCOPY * NBIN; i += TPB) p[i] = 0ull;
    }
    __syncthreads();

    unsigned long long* myh = s_hist[wid & (NCOPY - 1)];

    const float4* xl = (const float4*)(logits  + (size_t)row * ROWN);
    const int4*   tl = (const int4*)  (targets + (size_t)row * ROWN);
    const int4*   ml = (const int4*)  (mask    + (size_t)row * ROWN);

    float    sp = 0.f;
    unsigned np = 0u;

    const int base = blockIdx.x * TPB + tid;

    #pragma unroll 4
    for (int it = 0; it < ITERS; it++) {
        const int i = base + it * (BPR * TPB);
        float4 x4 = xl[i];
        int4   t4 = tl[i];
        int4   m4 = ml[i];

        float xs[4] = {x4.x, x4.y, x4.z, x4.w};
        int   ts[4] = {t4.x, t4.y, t4.z, t4.w};
        int   ms[4] = {m4.x, m4.y, m4.z, m4.w};

        #pragma unroll
        for (int k = 0; k < 4; k++) {
            float x = xs[k];
            int   t = ts[k];          // {0,1}
            int   m = ms[k];          // {0,1}
            // s = log1p(exp(-|x|))  >= 0
            float s = __logf(1.f + __expf(-fabsf(x)));
            // x' = t ? -x : x   (sign-flip via bit trick; t in {0,1})
            float xf = __int_as_float(__float_as_int(x) ^ (t << 31));
            // bce = s + max(x',0)   (bit-identical to max(x,0)-x*t+s)
            float bce = s + fmaxf(xf, 0.f);

            int is_pos = m & t;
            sp += is_pos ? bce : 0.f;     // predicated FADD
            np += (unsigned)is_pos;

            if (m & (t ^ 1)) {            // negative in tissue
                unsigned bin = __float_as_uint(bce) >> 21;    // < 2048
                unsigned su  = (unsigned)(bce * SUMSCALE + 0.5f);
                unsigned long long pk = (1ull << CNT_SHIFT)
                                      | (unsigned long long)su;
                atomicAdd(&myh[bin], pk);
            }
        }
    }

    // reduce positives
    #pragma unroll
    for (int o = 16; o > 0; o >>= 1) {
        sp += __shfl_down_sync(0xffffffffu, sp, o);
        np += __shfl_down_sync(0xffffffffu, np, o);
    }
    if (lane == 0) { r_sp[wid] = sp; r_np[wid] = np; }
    __syncthreads();

    if (tid == 0) {
        float bsp = 0.f; unsigned bnp = 0u;
        #pragma unroll
        for (int w = 0; w < TPB / 32; w++) { bsp += r_sp[w]; bnp += r_np[w]; }
        atomicAdd(&g_sum_pos[row], bsp);
        atomicAdd(&g_n_pos[row],   bnp);
    }

    // flush merged copies (sparse: ~30-60 hot bins)
    for (int b = tid; b < NBIN; b += TPB) {
        unsigned long long v = s_hist[0][b] + s_hist[1][b];
        if (v) atomicAdd(&g_hist[row][b], v);
    }

    __threadfence();
    if (tid == 0) {
        unsigned old = atomicAdd(&g_row_done[row], 1u);
        sh_last = (old == BPR - 1) ? 1 : 0;
    }
    __syncthreads();
    if (!sh_last) return;

    // ============ per-row selection (last block of this row) ============
    __threadfence();   // acquire: see all other blocks' hist/accumulator writes

    const float fnpos  = (float)g_n_pos[row];
    const float sp_row = g_sum_pos[row];

    unsigned cnt8[8];
    float    sum8[8];
    unsigned csum = 0u;
    float    fsum = 0.f;
    #pragma unroll
    for (int k = 0; k < 8; k++) {
        unsigned long long v = g_hist[row][tid * 8 + k];
        cnt8[k] = (unsigned)(v >> CNT_SHIFT);
        sum8[k] = (float)(v & SUM_MASK) * INV_SUMSCALE;
        csum += cnt8[k];
        fsum += sum8[k];
    }

    // intra-warp inclusive suffix scan (lane i gets sum over lanes i..31)
    unsigned ci = csum; float fi = fsum;
    #pragma unroll
    for (int off = 1; off < 32; off <<= 1) {
        unsigned c2 = __shfl_down_sync(0xffffffffu, ci, off);
        float    f2 = __shfl_down_sync(0xffffffffu, fi, off);
        if (lane + off < 32) { ci += c2; fi += f2; }
    }
    if (lane == 0) { s_wc[wid] = ci; s_wf[wid] = fi; }
    if (tid == 0) sh_kept = 0.f;
    __syncthreads();

    if (tid == 0) {   // tiny 8-entry suffix-exclusive over warp totals
        unsigned ca = 0u; float sa = 0.f;
        for (int w = (TPB / 32) - 1; w >= 0; w--) {
            s_wca[w] = ca; s_wfa[w] = sa;
            ca += s_wc[w]; sa += s_wf[w];
        }
        sh_nneg = ca;
    }
    __syncthreads();

    const float fnneg = (float)sh_nneg;
    const float jf    = fminf(fmaxf(K_ALL - fnpos, 0.f), fnneg);
    const unsigned ju = (unsigned)jf;

    if (ju > 0u) {
        // exclusive "strictly above this thread's chunk"
        unsigned ca = s_wca[wid] + (ci - csum);
        float    sa = s_wfa[wid] + (fi - fsum);
        #pragma unroll
        for (int k = 7; k >= 0; k--) {   // walk bins high -> low
            unsigned c = cnt8[k];
            if (c && ca < ju && ca + c >= ju) {
                float r    = (float)(ju - ca);
                float mean = sum8[k] / (float)c;
                sh_kept = sa + r * mean;     // exactly one thread matches
            }
            ca += c;
            sa += sum8[k];
        }
    }

    // cleanup for next graph replay (all reads of this row's globals done)
    #pragma unroll
    for (int k = 0; k < 8; k++) g_hist[row][tid * 8 + k] = 0ull;
    if (tid == 0) {
        g_sum_pos[row]  = 0.f;
        g_n_pos[row]    = 0u;
        g_row_done[row] = 0u;
    }
    __syncthreads();

    if (tid == 0) {
        float kkeep = fnpos + jf;
        float ps = (kkeep > 0.f)
                 ? (sp_row + sh_kept) / fmaxf(kkeep, 1.f)
                 : 0.f;
        g_per[row] = ps;
        __threadfence();
        unsigned old = atomicAdd(&g_done, 1u);
        if (old == NROW - 1) {
            __threadfence();
            g_done = 0u;                  // reset for next replay
            volatile float* vp = g_per;
            float tot = 0.f;
            #pragma unroll
            for (int r = 0; r < NROW; r++) tot += vp[r];
            d_out[0] = tot * (1.f / (float)NROW);
        }
    }
}

// ---------------------------------------------------------------
extern "C" void kernel_launch(void* const* d_in, const int* in_sizes, int n_in,
                              void* d_out, int out_size)
{
    (void)in_sizes; (void)n_in; (void)out_size;
    const float* logits  = (const float*)d_in[0];
    const int*   targets = (const int*)d_in[1];
    const int*   mask    = (const int*)d_in[2];
    float*       out     = (float*)d_out;

    dim3 grid(BPR, NROW);
    ohem_fused<<<grid, TPB>>>(logits, targets, mask, out);
}

// round 10
// speedup vs baseline: 2.3878x; 1.5548x over previous
#include <cuda_runtime.h>

#define NROW 8
#define ROWN (1 << 20)          // elements per batch row
#define N4   (ROWN / 4)         // float4 count per row
#define NLOW 512                // low-bin histogram size (bins 0..511)
#define PIVOT 0.25f             // bce < PIVOT -> histogram path (bin < 500)
#define NBIN 2048               // full bins (fallback kernel only)
#define BPR  76                 // 608 blocks ~= 4/SM on 152 SMs, one wave
#define TPB  256
#define K_ALL 524288u           // max(1, int(N * 0.5))
#define SUMSCALE 4194304.0f     // 2^22 fixed-point scale for packed sums
#define INV_SUMSCALE 2.384185791015625e-7f   // 2^-22
#define CNT_SHIFT 44
#define SUM_MASK ((1ull << CNT_SHIFT) - 1ull)

// ---- global scratch (zero-initialized at load; tails restore zeros) ----
__device__ unsigned long long g_hist[NROW][NLOW];
__device__ float    g_sum_pos[NROW];
__device__ unsigned g_n_pos[NROW];
__device__ float    g_sum_hi[NROW];
__device__ unsigned g_n_hi[NROW];
__device__ unsigned g_row_done[NROW];
__device__ int      g_need_fb[NROW];
__device__ float    g_per[NROW];
__device__ unsigned g_done2;

// ---------------------------------------------------------------
// Kernel 1: streaming BCE; low-loss negatives -> tiny shared hist,
// high-loss negatives -> register accumulators. Last block per row
// resolves selection if the boundary lies inside the low histogram.
// grid = (BPR, NROW), block = TPB
// ---------------------------------------------------------------
__global__ __launch_bounds__(TPB, 4) void ohem_main(
    const float* __restrict__ logits,
    const int*   __restrict__ targets,
    const int*   __restrict__ mask)
{
    __shared__ unsigned long long s_hist[NLOW];
    __shared__ float    r_sp[TPB / 32], r_sh[TPB / 32];
    __shared__ unsigned r_np[TPB / 32], r_nh[TPB / 32];
    __shared__ unsigned s_wc[TPB / 32], s_wca[TPB / 32];
    __shared__ float    s_wf[TPB / 32], s_wfa[TPB / 32];
    __shared__ float    sh_kept;
    __shared__ unsigned sh_nlow;
    __shared__ int      sh_last;

    const int row  = blockIdx.y;
    const int tid  = threadIdx.x;
    const int lane = tid & 31;
    const int wid  = tid >> 5;

    #pragma unroll
    for (int i = tid; i < NLOW; i += TPB) s_hist[i] = 0ull;
    __syncthreads();

    const float4* xl = (const float4*)(logits  + (size_t)row * ROWN);
    const int4*   tl = (const int4*)  (targets + (size_t)row * ROWN);
    const int4*   ml = (const int4*)  (mask    + (size_t)row * ROWN);

    float    sp = 0.f, sh = 0.f;
    unsigned np = 0u,  nh = 0u;

    const int stride = BPR * TPB;

    #pragma unroll 4
    for (int i = blockIdx.x * TPB + tid; i < N4; i += stride) {
        float4 x4 = xl[i];
        int4   t4 = tl[i];
        int4   m4 = ml[i];

        float xs[4] = {x4.x, x4.y, x4.z, x4.w};
        int   ts[4] = {t4.x, t4.y, t4.z, t4.w};
        int   ms[4] = {m4.x, m4.y, m4.z, m4.w};

        #pragma unroll
        for (int k = 0; k < 4; k++) {
            float x = xs[k];
            int   t = ts[k];          // {0,1}
            int   m = ms[k];          // {0,1}
            float s = __logf(1.f + __expf(-fabsf(x)));
            float xf = __int_as_float(__float_as_int(x) ^ (t << 31));
            float bce = s + fmaxf(xf, 0.f);   // == max(x,0)-x*t+log1p(exp(-|x|))

            int is_pos = m & t;
            int is_neg = m & (t ^ 1);
            sp += is_pos ? bce : 0.f;
            np += (unsigned)is_pos;

            int hi = is_neg & (bce >= PIVOT);
            sh += hi ? bce : 0.f;             // predicated, no atomic
            nh += (unsigned)hi;

            if (is_neg & (bce < PIVOT)) {     // rare (~2.6% of elements)
                unsigned bin = __float_as_uint(bce) >> 21;    // < 500
                unsigned long long pk = (1ull << CNT_SHIFT)
                    | (unsigned long long)(unsigned)(bce * SUMSCALE + 0.5f);
                atomicAdd(&s_hist[bin], pk);
            }
        }
    }

    // block reduce sp/np/sh/nh
    #pragma unroll
    for (int o = 16; o > 0; o >>= 1) {
        sp += __shfl_down_sync(0xffffffffu, sp, o);
        sh += __shfl_down_sync(0xffffffffu, sh, o);
        np += __shfl_down_sync(0xffffffffu, np, o);
        nh += __shfl_down_sync(0xffffffffu, nh, o);
    }
    if (lane == 0) { r_sp[wid] = sp; r_sh[wid] = sh; r_np[wid] = np; r_nh[wid] = nh; }
    __syncthreads();

    if (tid == 0) {
        float bsp = 0.f, bsh = 0.f; unsigned bnp = 0u, bnh = 0u;
        #pragma unroll
        for (int w = 0; w < TPB / 32; w++) {
            bsp += r_sp[w]; bsh += r_sh[w]; bnp += r_np[w]; bnh += r_nh[w];
        }
        atomicAdd(&g_sum_pos[row], bsp);
        atomicAdd(&g_sum_hi[row],  bsh);
        atomicAdd(&g_n_pos[row],   bnp);
        atomicAdd(&g_n_hi[row],    bnh);
    }

    // flush low histogram (sparse)
    for (int b = tid; b < NLOW; b += TPB) {
        unsigned long long v = s_hist[b];
        if (v) atomicAdd(&g_hist[row][b], v);
    }

    __threadfence();
    if (tid == 0) {
        unsigned old = atomicAdd(&g_row_done[row], 1u);
        sh_last = (old == BPR - 1) ? 1 : 0;
    }
    __syncthreads();
    if (!sh_last) return;

    // ============ per-row selection (last block of this row) ============
    __threadfence();   // acquire

    const unsigned np_row = g_n_pos[row];
    const float    sp_row = g_sum_pos[row];
    const unsigned nh_row = g_n_hi[row];
    const float    sh_row = g_sum_hi[row];

    unsigned cnt2[2];
    float    sum2[2];
    unsigned csum = 0u;
    float    fsum = 0.f;
    #pragma unroll
    for (int k = 0; k < 2; k++) {
        unsigned long long v = g_hist[row][tid * 2 + k];
        cnt2[k] = (unsigned)(v >> CNT_SHIFT);
        sum2[k] = (float)(v & SUM_MASK) * INV_SUMSCALE;
        csum += cnt2[k];
        fsum += sum2[k];
    }

    // intra-warp inclusive suffix scan
    unsigned ci = csum; float fi = fsum;
    #pragma unroll
    for (int off = 1; off < 32; off <<= 1) {
        unsigned c2 = __shfl_down_sync(0xffffffffu, ci, off);
        float    f2 = __shfl_down_sync(0xffffffffu, fi, off);
        if (lane + off < 32) { ci += c2; fi += f2; }
    }
    if (lane == 0) { s_wc[wid] = ci; s_wf[wid] = fi; }
    if (tid == 0) sh_kept = 0.f;
    __syncthreads();

    if (tid == 0) {
        unsigned ca = 0u; float sa = 0.f;
        for (int w = (TPB / 32) - 1; w >= 0; w--) {
            s_wca[w] = ca; s_wfa[w] = sa;
            ca += s_wc[w]; sa += s_wf[w];
        }
        sh_nlow = ca;
    }
    __syncthreads();

    const unsigned count_low = sh_nlow;
    const unsigned n_neg     = count_low + nh_row;
    const unsigned avail     = (K_ALL > np_row) ? (K_ALL - np_row) : 0u;
    const unsigned j         = (avail < n_neg) ? avail : n_neg;

    const int resolved = (j >= nh_row);
    const unsigned ju  = resolved ? (j - nh_row) : 0u;   // top-ju of low hist

    if (ju > 0u) {
        unsigned ca = s_wca[wid] + (ci - csum);
        float    sa = s_wfa[wid] + (fi - fsum);
        #pragma unroll
        for (int k = 1; k >= 0; k--) {   // walk bins high -> low
            unsigned c = cnt2[k];
            if (c && ca < ju && ca + c >= ju) {
                float r    = (float)(ju - ca);
                float mean = sum2[k] / (float)c;
                sh_kept = sa + r * mean;
            }
            ca += c;
            sa += sum2[k];
        }
    }

    // cleanup for next graph replay
    #pragma unroll
    for (int k = 0; k < 2; k++) g_hist[row][tid * 2 + k] = 0ull;
    if (tid == 0) {
        g_sum_pos[row]  = 0.f;  g_n_pos[row] = 0u;
        g_sum_hi[row]   = 0.f;  g_n_hi[row]  = 0u;
        g_row_done[row] = 0u;
    }
    __syncthreads();

    if (tid == 0) {
        if (resolved) {
            float kkeep = (float)(np_row + j);
            float kept  = sh_row + sh_kept;
            float ps = (kkeep > 0.f) ? (sp_row + kept) / fmaxf(kkeep, 1.f) : 0.f;
            g_per[row]     = ps;
            g_need_fb[row] = 0;
        } else {
            g_need_fb[row] = 1;    // boundary above pivot: rare, kernel2 resolves
        }
    }
}

// ---------------------------------------------------------------
// Kernel 2: per-row fallback (full-precision recompute) + final mean.
// grid = NROW, block = TPB. Common case: flag==0, near-instant.
// ---------------------------------------------------------------
__global__ __launch_bounds__(TPB) void ohem_finish(
    const float* __restrict__ logits,
    const int*   __restrict__ targets,
    const int*   __restrict__ mask,
    float*       __restrict__ d_out)
{
    const int row  = blockIdx.x;
    const int tid  = threadIdx.x;
    const int lane = tid & 31;
    const int wid  = tid >> 5;

    __shared__ unsigned long long s_hist[NBIN];
    __shared__ float    r_sp[TPB / 32];
    __shared__ unsigned r_np[TPB / 32];
    __shared__ unsigned s_wc[TPB / 32], s_wca[TPB / 32];
    __shared__ float    s_wf[TPB / 32], s_wfa[TPB / 32];
    __shared__ float    sh_kept;
    __shared__ unsigned sh_nneg;

    if (g_need_fb[row]) {
        // full 2048-bin recompute of this row (slow; correctness-only path)
        for (int i = tid; i < NBIN; i += TPB) s_hist[i] = 0ull;
        __syncthreads();

        const float4* xl = (const float4*)(logits  + (size_t)row * ROWN);
        const int4*   tl = (const int4*)  (targets + (size_t)row * ROWN);
        const int4*   ml = (const int4*)  (mask    + (size_t)row * ROWN);

        float sp = 0.f; unsigned np = 0u;
        for (int i = tid; i < N4; i += TPB) {
            float4 x4 = xl[i]; int4 t4 = tl[i]; int4 m4 = ml[i];
            float xs[4] = {x4.x, x4.y, x4.z, x4.w};
            int   ts[4] = {t4.x, t4.y, t4.z, t4.w};
            int   ms[4] = {m4.x, m4.y, m4.z, m4.w};
            #pragma unroll
            for (int k = 0; k < 4; k++) {
                float x = xs[k]; int t = ts[k]; int m = ms[k];
                float s = __logf(1.f + __expf(-fabsf(x)));
                float xf = __int_as_float(__float_as_int(x) ^ (t << 31));
                float bce = fmaxf(s + fmaxf(xf, 0.f), 0.f);
                if (m & t) { sp += bce; np++; }
                if (m & (t ^ 1)) {
                    unsigned bin = __float_as_uint(bce) >> 21;   // <= 1020
                    unsigned long long pk = (1ull << CNT_SHIFT)
                        | (unsigned long long)(unsigned)(bce * SUMSCALE + 0.5f);
                    atomicAdd(&s_hist[bin], pk);
                }
            }
        }
        #pragma unroll
        for (int o = 16; o > 0; o >>= 1) {
            sp += __shfl_down_sync(0xffffffffu, sp, o);
            np += __shfl_down_sync(0xffffffffu, np, o);
        }
        if (lane == 0) { r_sp[wid] = sp; r_np[wid] = np; }
        __syncthreads();

        unsigned cnt8[8]; float sum8[8];
        unsigned csum = 0u; float fsum = 0.f;
        #pragma unroll
        for (int k = 0; k < 8; k++) {
            unsigned long long v = s_hist[tid * 8 + k];
            cnt8[k] = (unsigned)(v >> CNT_SHIFT);
            sum8[k] = (float)(v & SUM_MASK) * INV_SUMSCALE;
            csum += cnt8[k]; fsum += sum8[k];
        }
        unsigned ci = csum; float fi = fsum;
        #pragma unroll
        for (int off = 1; off < 32; off <<= 1) {
            unsigned c2 = __shfl_down_sync(0xffffffffu, ci, off);
            float    f2 = __shfl_down_sync(0xffffffffu, fi, off);
            if (lane + off < 32) { ci += c2; fi += f2; }
        }
        if (lane == 0) { s_wc[wid] = ci; s_wf[wid] = fi; }
        if (tid == 0) sh_kept = 0.f;
        __syncthreads();
        if (tid == 0) {
            unsigned ca = 0u; float sa = 0.f;
            for (int w = (TPB / 32) - 1; w >= 0; w--) {
                s_wca[w] = ca; s_wfa[w] = sa;
                ca += s_wc[w]; sa += s_wf[w];
            }
            sh_nneg = ca;
        }
        __syncthreads();

        float bsp = 0.f; unsigned bnp = 0u;
        if (tid == 0) {
            #pragma unroll
            for (int w = 0; w < TPB / 32; w++) { bsp += r_sp[w]; bnp += r_np[w]; }
        }
        bnp = __shfl_sync(0xffffffffu, bnp, 0);   // broadcast within warp0 only; others unused
        __syncthreads();

        const unsigned np_row = (tid == 0) ? bnp : 0u;   // only tid0 uses
        const unsigned n_neg  = sh_nneg;
        // all threads need j for select: recompute from shared
        __shared__ unsigned sh_np;
        if (tid == 0) sh_np = bnp;
        __syncthreads();
        const unsigned npr   = sh_np;
        const unsigned avail = (K_ALL > npr) ? (K_ALL - npr) : 0u;
        const unsigned ju    = (avail < n_neg) ? avail : n_neg;

        if (ju > 0u) {
            unsigned ca = s_wca[wid] + (ci - csum);
            float    sa = s_wfa[wid] + (fi - fsum);
            #pragma unroll
            for (int k = 7; k >= 0; k--) {
                unsigned c = cnt8[k];
                if (c && ca < ju && ca + c >= ju) {
                    float r    = (float)(ju - ca);
                    float mean = sum8[k] / (float)c;
                    sh_kept = sa + r * mean;
                }
                ca += c;
                sa += sum8[k];
            }
        }
        __syncthreads();

        if (tid == 0) {
            float kkeep = (float)(npr + ju);
            float ps = (kkeep > 0.f) ? (bsp + sh_kept) / fmaxf(kkeep, 1.f) : 0.f;
            g_per[row]     = ps;
            g_need_fb[row] = 0;
        }
        __syncthreads();
        (void)np_row;
    }

    if (tid == 0) {
        __threadfence();
        unsigned old = atomicAdd(&g_done2, 1u);
        if (old == NROW - 1) {
            __threadfence();
            g_done2 = 0u;
            volatile float* vp = g_per;
            float tot = 0.f;
            #pragma unroll
            for (int r = 0; r < NROW; r++) tot += vp[r];
            d_out[0] = tot * (1.f / (float)NROW);
        }
    }
}

// ---------------------------------------------------------------
extern "C" void kernel_launch(void* const* d_in, const int* in_sizes, int n_in,
                              void* d_out, int out_size)
{
    (void)in_sizes; (void)n_in; (void)out_size;
    const float* logits  = (const float*)d_in[0];
    const int*   targets = (const int*)d_in[1];
    const int*   mask    = (const int*)d_in[2];
    float*       out     = (float*)d_out;

    dim3 grid(BPR, NROW);
    ohem_main<<<grid, TPB>>>(logits, targets, mask);
    ohem_finish<<<NROW, TPB>>>(logits, targets, mask, out);
}